// round 16
// baseline (speedup 1.0000x reference)
#include <cuda_runtime.h>
#include <cuda_fp16.h>
#include <cstdint>

#define D 128
#define EPSV 1e-5f
#define ROWS 64

// ---------------- smem layout (byte offsets into dynamic smem) ----------------
#define AS       264            // fp16 elems per A row (256 cols + 8 pad)
#define A_H      0u             // 64 x 264 fp16 = 33792 B
#define SM_BIAS  33792u         // 9 vecs x 128 fp32 = 4608
#define SM_PART  38400u         // 64 rows x 4 colgroups x float2 = 2048
#define SM_SRC   40448u
#define SM_DST   40704u
#define SMEM_DYN 40960u

// ---------------- scratch (alloc-free) ----------------
__device__ float g_agg[80000 * D];
__device__ float g_h1[80000 * D];
// prepped weights in mma.sync B-fragment order:
// per k16-step: 4 colgroups x 32 lanes x 32 B = 4096 B
__device__ __align__(16) unsigned char g_Wprep[2 * 262144];
#define OFF_BW1 0u
#define OFF_BW2 65536u
#define OFF_SW1 98304u
#define OFF_SW2 163840u
#define OFF_HW  196608u
#define WLEVEL  262144u

// ---------------- PTX helpers (base ISA: valid on compute_103) ----------------
__device__ __forceinline__ uint32_t smem_u32(const void* p) {
    uint32_t a;
    asm("{ .reg .u64 t; cvta.to.shared.u64 t, %1; cvt.u32.u64 %0, t; }" : "=r"(a) : "l"(p));
    return a;
}
#define LDSM4(r, addr) \
    asm volatile("ldmatrix.sync.aligned.m8n8.x4.shared.b16 {%0,%1,%2,%3}, [%4];" \
                 : "=r"((r)[0]), "=r"((r)[1]), "=r"((r)[2]), "=r"((r)[3]) : "r"(addr))
#define MMA16816(dd, a, b0, b1) \
    asm volatile("mma.sync.aligned.m16n8k16.row.col.f32.f16.f16.f32 " \
                 "{%0,%1,%2,%3},{%4,%5,%6,%7},{%8,%9},{%0,%1,%2,%3};" \
                 : "+f"((dd)[0]), "+f"((dd)[1]), "+f"((dd)[2]), "+f"((dd)[3]) \
                 : "r"((a)[0]), "r"((a)[1]), "r"((a)[2]), "r"((a)[3]), "r"(b0), "r"(b1))

// ---------------- gather: 64 rows x 128 fp32 cols -> A fp16 tile at col0 (512 thr) ----------------
__device__ __forceinline__ void gather64(unsigned char* sm, const float4* __restrict__ src,
                                         const int* idx, long long row0, int col0,
                                         int nvalid, int t) {
    int r = t >> 3, q = t & 7;
    int cbase = col0 + q * 16;
    bool ok = r < nvalid;
    long long sr = idx ? (ok ? (long long)idx[r] : 0) : (row0 + r);
    const float4* p = src + sr * 32 + q * 4;
#pragma unroll
    for (int j = 0; j < 4; j++) {
        float4 v = ok ? __ldg(p + j) : make_float4(0.f, 0.f, 0.f, 0.f);
        __half2 h0 = __floats2half2_rn(v.x, v.y);
        __half2 h1 = __floats2half2_rn(v.z, v.w);
        uint32_t off = (uint32_t)(r * AS + cbase + j * 4) * 2u;
        *(uint2*)(sm + A_H + off) =
            make_uint2(*reinterpret_cast<uint32_t*>(&h0), *reinterpret_cast<uint32_t*>(&h1));
    }
}

// ---------------- one GEMM layer: K = NK16*16, A cols start at kbase ----------------
// 16 warps as 4row x 4col grid: warp tile = 16 rows x 32 cols. d[16] accumulators.
// W fragments LDG'd directly from gmem (fragment-ordered). NO syncs inside.
template <int NK16>
__device__ __forceinline__ void run_layer(uint32_t smb,
                                          const unsigned char* __restrict__ w,
                                          int kbase, float* d, int lane, int warp) {
#pragma unroll
    for (int i = 0; i < 16; i++) d[i] = 0.f;

    int wrow = (warp & 3) * 16, cg = warp >> 2;
    const uint32_t aconst = smb + A_H +
        (uint32_t)((wrow + (lane & 7) + ((lane >> 3) & 1) * 8) * AS + (lane >> 4) * 8) * 2u;
    const unsigned char* wbase = w + (uint32_t)cg * 1024u + (uint32_t)lane * 32u;

#pragma unroll 2
    for (int ks = 0; ks < NK16; ks++) {
        int4 v0 = __ldg((const int4*)(wbase + (uint32_t)ks * 4096u));
        int4 v1 = __ldg((const int4*)(wbase + (uint32_t)ks * 4096u + 16u));
        uint32_t ah[4];
        LDSM4(ah, aconst + (uint32_t)(kbase + ks * 16) * 2u);
        MMA16816(d + 0,  ah, (uint32_t)v0.x, (uint32_t)v0.y);
        MMA16816(d + 4,  ah, (uint32_t)v0.z, (uint32_t)v0.w);
        MMA16816(d + 8,  ah, (uint32_t)v1.x, (uint32_t)v1.y);
        MMA16816(d + 12, ah, (uint32_t)v1.z, (uint32_t)v1.w);
    }
}

// ---------------- LN stats core: bias + stats + cross-warp reduce (ONE sync) ----------------
__device__ __forceinline__ void ln_stats(unsigned char* sm, float* d, const float* bs,
                                         float* m, float* rv, int lane, int warp) {
    float2* part = (float2*)(sm + SM_PART);
    int wcol = (warp >> 2) * 32, cg = warp >> 2;
    int r0 = (warp & 3) * 16 + (lane >> 2);
    int r1 = r0 + 8;

    float s0 = 0.f, q0 = 0.f, s1 = 0.f, q1 = 0.f;
#pragma unroll
    for (int nt = 0; nt < 4; nt++) {
        int di = nt * 4;
        int c0 = wcol + nt * 8 + (lane & 3) * 2;
        float x0 = d[di + 0] + bs[c0];
        float x1 = d[di + 1] + bs[c0 + 1];
        float x2 = d[di + 2] + bs[c0];
        float x3 = d[di + 3] + bs[c0 + 1];
        d[di + 0] = x0; d[di + 1] = x1; d[di + 2] = x2; d[di + 3] = x3;
        s0 += x0 + x1; q0 += x0 * x0 + x1 * x1;
        s1 += x2 + x3; q1 += x2 * x2 + x3 * x3;
    }
    s0 += __shfl_xor_sync(0xffffffffu, s0, 1); s0 += __shfl_xor_sync(0xffffffffu, s0, 2);
    q0 += __shfl_xor_sync(0xffffffffu, q0, 1); q0 += __shfl_xor_sync(0xffffffffu, q0, 2);
    s1 += __shfl_xor_sync(0xffffffffu, s1, 1); s1 += __shfl_xor_sync(0xffffffffu, s1, 2);
    q1 += __shfl_xor_sync(0xffffffffu, q1, 1); q1 += __shfl_xor_sync(0xffffffffu, q1, 2);
    if ((lane & 3) == 0) {
        part[r0 * 4 + cg] = make_float2(s0, q0);
        part[r1 * 4 + cg] = make_float2(s1, q1);
    }
    __syncthreads();   // partials visible AND all mainloop A-LDSM done

#pragma unroll
    for (int j = 0; j < 2; j++) {
        int row = (j == 0) ? r0 : r1;
        float2 p0 = part[row * 4 + 0], p1 = part[row * 4 + 1];
        float2 p2 = part[row * 4 + 2], p3 = part[row * 4 + 3];
        float sum = p0.x + p1.x + p2.x + p3.x;
        float qq  = p0.y + p1.y + p2.y + p3.y;
        m[j]  = sum * (1.f / 128.f);
        rv[j] = rsqrtf(qq * (1.f / 128.f) - m[j] * m[j] + EPSV);
    }
}

// ---------------- epilogue A: LN+ReLU -> fp16 back into A tile at dstcol (ends with sync) ----------------
__device__ __forceinline__ void epilogue_smem(unsigned char* sm, float* d, int L,
                                              int dstcol, int lane, int warp) {
    const float* bs  = (const float*)(sm + SM_BIAS) + L * 384;
    const float* gs  = bs + 128;
    const float* bes = bs + 256;
    float m[2], rv[2];
    ln_stats(sm, d, bs, m, rv, lane, warp);

    int wcol = (warp >> 2) * 32;
    int r0 = (warp & 3) * 16 + (lane >> 2);
    int r1 = r0 + 8;
#pragma unroll
    for (int nt = 0; nt < 4; nt++) {
        int di = nt * 4;
        int c0 = wcol + nt * 8 + (lane & 3) * 2;
        float y0 = fmaxf(fmaf((d[di + 0] - m[0]) * rv[0], gs[c0],     bes[c0]),     0.f);
        float y1 = fmaxf(fmaf((d[di + 1] - m[0]) * rv[0], gs[c0 + 1], bes[c0 + 1]), 0.f);
        float y2 = fmaxf(fmaf((d[di + 2] - m[1]) * rv[1], gs[c0],     bes[c0]),     0.f);
        float y3 = fmaxf(fmaf((d[di + 3] - m[1]) * rv[1], gs[c0 + 1], bes[c0 + 1]), 0.f);
        __half2 h0 = __floats2half2_rn(y0, y1);
        __half2 h1 = __floats2half2_rn(y2, y3);
        *(uint32_t*)(sm + A_H + (uint32_t)(r0 * AS + dstcol + c0) * 2u) =
            *reinterpret_cast<uint32_t*>(&h0);
        *(uint32_t*)(sm + A_H + (uint32_t)(r1 * AS + dstcol + c0) * 2u) =
            *reinterpret_cast<uint32_t*>(&h1);
    }
    __syncthreads();   // A-tile writes visible to next layer
}

// ---------------- epilogue B: LN+ReLU -> direct emit (atomics to agg, or STG to out) ----------------
__device__ __forceinline__ void epilogue_emit(unsigned char* sm, float* d, int L,
                                              float* __restrict__ agg, const int* dsm,
                                              float* __restrict__ outp, long long row0,
                                              int nvalid, int lane, int warp) {
    const float* bs  = (const float*)(sm + SM_BIAS) + L * 384;
    const float* gs  = bs + 128;
    const float* bes = bs + 256;
    float m[2], rv[2];
    ln_stats(sm, d, bs, m, rv, lane, warp);

    int wcol = (warp >> 2) * 32;
    int r0 = (warp & 3) * 16 + (lane >> 2);
    int r1 = r0 + 8;
    bool ok0 = r0 < nvalid, ok1 = r1 < nvalid;
    size_t base0 = 0, base1 = 0;
    if (agg) {
        if (ok0) base0 = (size_t)dsm[r0] * 128;
        if (ok1) base1 = (size_t)dsm[r1] * 128;
    } else {
        base0 = (size_t)(row0 + r0) * 128;
        base1 = (size_t)(row0 + r1) * 128;
    }
#pragma unroll
    for (int nt = 0; nt < 4; nt++) {
        int di = nt * 4;
        int c0 = wcol + nt * 8 + (lane & 3) * 2;
        float y0 = fmaxf(fmaf((d[di + 0] - m[0]) * rv[0], gs[c0],     bes[c0]),     0.f);
        float y1 = fmaxf(fmaf((d[di + 1] - m[0]) * rv[0], gs[c0 + 1], bes[c0 + 1]), 0.f);
        float y2 = fmaxf(fmaf((d[di + 2] - m[1]) * rv[1], gs[c0],     bes[c0]),     0.f);
        float y3 = fmaxf(fmaf((d[di + 3] - m[1]) * rv[1], gs[c0 + 1], bes[c0 + 1]), 0.f);
        if (agg) {
            if (ok0) atomicAdd((float2*)(agg + base0 + c0), make_float2(y0, y1));
            if (ok1) atomicAdd((float2*)(agg + base1 + c0), make_float2(y2, y3));
        } else {
            if (ok0) *(float2*)(outp + base0 + c0) = make_float2(y0, y1);
            if (ok1) *(float2*)(outp + base1 + c0) = make_float2(y2, y3);
        }
    }
}

// ---------------- edge kernel ----------------
__global__ __launch_bounds__(512, 2)
void edge_kernel(const float* __restrict__ h, const float* __restrict__ bond,
                 const int* __restrict__ src, const int* __restrict__ dst,
                 const unsigned char* __restrict__ wlev,
                 const float* __restrict__ b1, const float* __restrict__ g1, const float* __restrict__ be1,
                 const float* __restrict__ b2, const float* __restrict__ g2, const float* __restrict__ be2,
                 float* __restrict__ agg, int E) {
    extern __shared__ __align__(16) unsigned char sm[];
    uint32_t smb = smem_u32(sm);
    int t = threadIdx.x, lane = t & 31, warp = t >> 5;
    long long e0 = (long long)blockIdx.x * ROWS;
    int nvalid = (int)min((long long)ROWS, (long long)E - e0);

    int* ssm = (int*)(sm + SM_SRC);
    int* dsm = (int*)(sm + SM_DST);
    if (t < ROWS) {
        ssm[t] = (t < nvalid) ? src[e0 + t] : 0;
        dsm[t] = (t < nvalid) ? dst[e0 + t] : 0;
    }
    if (t >= 128 && t < 256) {
        int u = t - 128;
        float* pb = (float*)(sm + SM_BIAS);
        pb[0 * 128 + u] = __ldg(b1 + u);  pb[1 * 128 + u] = __ldg(g1 + u);  pb[2 * 128 + u] = __ldg(be1 + u);
        pb[3 * 128 + u] = __ldg(b2 + u);  pb[4 * 128 + u] = __ldg(g2 + u);  pb[5 * 128 + u] = __ldg(be2 + u);
    }
    __syncthreads();

    gather64(sm, (const float4*)h, ssm, 0, 0, nvalid, t);
    gather64(sm, (const float4*)bond, nullptr, e0, 128, nvalid, t);
    __syncthreads();

    float d[16];
    run_layer<16>(smb, wlev + OFF_BW1, 0, d, lane, warp);
    epilogue_smem(sm, d, 0, 0, lane, warp);
    run_layer<8>(smb, wlev + OFF_BW2, 0, d, lane, warp);
    epilogue_emit(sm, d, 1, agg, dsm, nullptr, 0, nvalid, lane, warp);
}

// ---------------- node kernel ----------------
__global__ __launch_bounds__(512, 2)
void node_kernel(const float* __restrict__ ax, const float* __restrict__ aggin,
                 const unsigned char* __restrict__ wlev,
                 const float* __restrict__ sb1, const float* __restrict__ sg1, const float* __restrict__ sbe1,
                 const float* __restrict__ sb2, const float* __restrict__ sg2, const float* __restrict__ sbe2,
                 const float* __restrict__ hb, const float* __restrict__ hg, const float* __restrict__ hbe,
                 float* __restrict__ out, int N) {
    extern __shared__ __align__(16) unsigned char sm[];
    uint32_t smb = smem_u32(sm);
    int t = threadIdx.x, lane = t & 31, warp = t >> 5;
    long long n0 = (long long)blockIdx.x * ROWS;
    int nvalid = (int)min((long long)ROWS, (long long)N - n0);

    if (t >= 128 && t < 256) {
        int u = t - 128;
        float* pb = (float*)(sm + SM_BIAS);
        pb[0 * 128 + u] = __ldg(sb1 + u); pb[1 * 128 + u] = __ldg(sg1 + u); pb[2 * 128 + u] = __ldg(sbe1 + u);
        pb[3 * 128 + u] = __ldg(sb2 + u); pb[4 * 128 + u] = __ldg(sg2 + u); pb[5 * 128 + u] = __ldg(sbe2 + u);
        pb[6 * 128 + u] = __ldg(hb + u);  pb[7 * 128 + u] = __ldg(hg + u);  pb[8 * 128 + u] = __ldg(hbe + u);
    }

    gather64(sm, (const float4*)ax, nullptr, n0, 0, nvalid, t);
    gather64(sm, (const float4*)aggin, nullptr, n0, 128, nvalid, t);
    __syncthreads();

    float d[16];
    run_layer<16>(smb, wlev + OFF_SW1, 0, d, lane, warp);
    epilogue_smem(sm, d, 0, 128, lane, warp);   // f1 -> cols 128..255 (keep ax)
    run_layer<8>(smb, wlev + OFF_SW2, 128, d, lane, warp);
    epilogue_smem(sm, d, 1, 128, lane, warp);   // f2 -> cols 128..255
    run_layer<16>(smb, wlev + OFF_HW, 0, d, lane, warp);
    epilogue_emit(sm, d, 2, nullptr, nullptr, out, n0, nvalid, lane, warp);
}

// ---------------- weight prep: fp32 W[K][128] -> mma B-fragment-ordered fp16 ----------------
__global__ void prep_kernel(const float* __restrict__ bW1, const float* __restrict__ bW2,
                            const float* __restrict__ sW1, const float* __restrict__ sW2,
                            const float* __restrict__ hW) {
    int level = blockIdx.y, bx = blockIdx.x, t = threadIdx.x;
    const float* W; int ks; uint32_t off; int K;
    if (bx < 16)      { W = bW1; ks = bx;      off = OFF_BW1; K = 256; }
    else if (bx < 24) { W = bW2; ks = bx - 16; off = OFF_BW2; K = 128; }
    else if (bx < 40) { W = sW1; ks = bx - 24; off = OFF_SW1; K = 256; }
    else if (bx < 48) { W = sW2; ks = bx - 40; off = OFF_SW2; K = 128; }
    else              { W = hW;  ks = bx - 48; off = OFF_HW;  K = 256; }

    const float* wsrc = W + (size_t)level * K * 128;
    int cg = t >> 5, lane = t & 31;
    unsigned char* dl = g_Wprep + (size_t)level * WLEVEL + off
                      + (size_t)ks * 4096u + (uint32_t)cg * 1024u + (uint32_t)lane * 32u;
    int kb = ks * 16 + (lane & 3) * 2;
#pragma unroll
    for (int nt = 0; nt < 4; nt++) {
        int n = cg * 32 + nt * 8 + (lane >> 2);
        __half2 b0 = __halves2half2(__float2half_rn(wsrc[kb * 128 + n]),
                                    __float2half_rn(wsrc[(kb + 1) * 128 + n]));
        __half2 b1 = __halves2half2(__float2half_rn(wsrc[(kb + 8) * 128 + n]),
                                    __float2half_rn(wsrc[(kb + 9) * 128 + n]));
        *(uint32_t*)(dl + nt * 8)     = *reinterpret_cast<uint32_t*>(&b0);
        *(uint32_t*)(dl + nt * 8 + 4) = *reinterpret_cast<uint32_t*>(&b1);
    }
}

// ---------------- kernel_launch ----------------
extern "C" void kernel_launch(void* const* d_in, const int* in_sizes, int n_in,
                              void* d_out, int out_size) {
    const float* subtree_h_top = (const float*)d_in[0];
    const float* atom_x_1      = (const float*)d_in[1];
    const float* atom_x_0      = (const float*)d_in[2];
    const float* bond_x_2      = (const float*)d_in[3];
    const float* bond_x_1      = (const float*)d_in[4];
    const float* branch_W1     = (const float*)d_in[5];
    const float* branch_b1     = (const float*)d_in[6];
    const float* branch_g1     = (const float*)d_in[7];
    const float* branch_beta1  = (const float*)d_in[8];
    const float* branch_W2     = (const float*)d_in[9];
    const float* branch_b2     = (const float*)d_in[10];
    const float* branch_g2     = (const float*)d_in[11];
    const float* branch_beta2  = (const float*)d_in[12];
    const float* sub_W1        = (const float*)d_in[13];
    const float* sub_b1        = (const float*)d_in[14];
    const float* sub_g1        = (const float*)d_in[15];
    const float* sub_beta1     = (const float*)d_in[16];
    const float* sub_W2        = (const float*)d_in[17];
    const float* sub_b2        = (const float*)d_in[18];
    const float* sub_g2        = (const float*)d_in[19];
    const float* sub_beta2     = (const float*)d_in[20];
    const float* head_W        = (const float*)d_in[21];
    const float* head_b        = (const float*)d_in[22];
    const float* head_g        = (const float*)d_in[23];
    const float* head_beta     = (const float*)d_in[24];
    const int*   src_2         = (const int*)d_in[25];
    const int*   dst_2         = (const int*)d_in[26];
    const int*   src_1         = (const int*)d_in[27];
    const int*   dst_1         = (const int*)d_in[28];

    const int n2 = in_sizes[0] / D;
    const int n1 = in_sizes[1] / D;
    const int n0 = in_sizes[2] / D;

    float* agg; cudaGetSymbolAddress((void**)&agg, g_agg);
    float* h1;  cudaGetSymbolAddress((void**)&h1,  g_h1);
    unsigned char* wprep; cudaGetSymbolAddress((void**)&wprep, g_Wprep);
    float* out = (float*)d_out;

    static bool attr_done = false;
    if (!attr_done) {
        cudaFuncSetAttribute(edge_kernel, cudaFuncAttributeMaxDynamicSharedMemorySize, SMEM_DYN);
        cudaFuncSetAttribute(node_kernel, cudaFuncAttributeMaxDynamicSharedMemorySize, SMEM_DYN);
        attr_done = true;
    }

    const int V = D;

    prep_kernel<<<dim3(64, 2), 128>>>(branch_W1, branch_W2, sub_W1, sub_W2, head_W);

    // level 0: n2 edges -> n1 nodes
    cudaMemsetAsync(agg, 0, (size_t)n1 * D * sizeof(float));
    edge_kernel<<<(n2 + ROWS - 1) / ROWS, 512, SMEM_DYN>>>(
        subtree_h_top, bond_x_2, src_2, dst_2, wprep,
        branch_b1, branch_g1, branch_beta1,
        branch_b2, branch_g2, branch_beta2, agg, n2);
    node_kernel<<<(n1 + ROWS - 1) / ROWS, 512, SMEM_DYN>>>(
        atom_x_1, agg, wprep,
        sub_b1, sub_g1, sub_beta1,
        sub_b2, sub_g2, sub_beta2,
        head_b, head_g, head_beta, h1, n1);

    // level 1: n1 edges -> n0 nodes
    cudaMemsetAsync(agg, 0, (size_t)n0 * D * sizeof(float));
    edge_kernel<<<(n1 + ROWS - 1) / ROWS, 512, SMEM_DYN>>>(
        h1, bond_x_1, src_1, dst_1, wprep + WLEVEL,
        branch_b1 + V, branch_g1 + V, branch_beta1 + V,
        branch_b2 + V, branch_g2 + V, branch_beta2 + V, agg, n1);
    node_kernel<<<(n0 + ROWS - 1) / ROWS, 512, SMEM_DYN>>>(
        atom_x_0, agg, wprep + WLEVEL,
        sub_b1 + V, sub_g1 + V, sub_beta1 + V,
        sub_b2 + V, sub_g2 + V, sub_beta2 + V,
        head_b + V, head_g + V, head_beta + V, out, n0);
}

// round 17
// speedup vs baseline: 1.1784x; 1.1784x over previous
#include <cuda_runtime.h>
#include <cuda_fp16.h>
#include <cstdint>

#define D 128
#define EPSV 1e-5f
#define ROWS 64

// ---------------- smem layout (byte offsets into dynamic smem) ----------------
#define AS       264            // fp16 elems per A row (256 cols + 8 pad)
#define A_H      0u             // 64 x 264 fp16 = 33792 B
#define SM_BIAS  33792u         // 9 vecs x 128 fp32 = 4608
#define SM_PART  38400u         // 64 rows x 4 colgroups x float2 = 2048
#define SM_SRC   40448u
#define SM_DST   40704u
#define SMEM_DYN 40960u

// ---------------- scratch (alloc-free) ----------------
__device__ float g_agg[80000 * D];
__device__ float g_h1[80000 * D];
// prepped weights in mma.sync B-fragment order:
// per k16-step: 4 colgroups x 32 lanes x 32 B = 4096 B
__device__ __align__(16) unsigned char g_Wprep[2 * 262144];
#define OFF_BW1 0u
#define OFF_BW2 65536u
#define OFF_SW1 98304u
#define OFF_SW2 163840u
#define OFF_HW  196608u
#define WLEVEL  262144u

// ---------------- PTX helpers (base ISA: valid on compute_103) ----------------
__device__ __forceinline__ uint32_t smem_u32(const void* p) {
    uint32_t a;
    asm("{ .reg .u64 t; cvta.to.shared.u64 t, %1; cvt.u32.u64 %0, t; }" : "=r"(a) : "l"(p));
    return a;
}
#define LDSM4(r, addr) \
    asm volatile("ldmatrix.sync.aligned.m8n8.x4.shared.b16 {%0,%1,%2,%3}, [%4];" \
                 : "=r"((r)[0]), "=r"((r)[1]), "=r"((r)[2]), "=r"((r)[3]) : "r"(addr))
#define MMA16816(dd, a, b0, b1) \
    asm volatile("mma.sync.aligned.m16n8k16.row.col.f32.f16.f16.f32 " \
                 "{%0,%1,%2,%3},{%4,%5,%6,%7},{%8,%9},{%0,%1,%2,%3};" \
                 : "+f"((dd)[0]), "+f"((dd)[1]), "+f"((dd)[2]), "+f"((dd)[3]) \
                 : "r"((a)[0]), "r"((a)[1]), "r"((a)[2]), "r"((a)[3]), "r"(b0), "r"(b1))

// ---------------- gather: 64 rows x 128 fp32 cols -> A fp16 tile at col0 ----------------
__device__ __forceinline__ void gather64(unsigned char* sm, const float4* __restrict__ src,
                                         const int* idx, long long row0, int col0,
                                         int nvalid, int t) {
    int r = t >> 2, q = t & 3;
    int cbase = col0 + q * 32;
    bool ok = r < nvalid;
    long long sr = idx ? (ok ? (long long)idx[r] : 0) : (row0 + r);
    const float4* p = src + sr * 32 + q * 8;
#pragma unroll
    for (int j = 0; j < 8; j++) {
        float4 v = ok ? __ldg(p + j) : make_float4(0.f, 0.f, 0.f, 0.f);
        __half2 h0 = __floats2half2_rn(v.x, v.y);
        __half2 h1 = __floats2half2_rn(v.z, v.w);
        uint32_t off = (uint32_t)(r * AS + cbase + j * 4) * 2u;
        *(uint2*)(sm + A_H + off) =
            make_uint2(*reinterpret_cast<uint32_t*>(&h0), *reinterpret_cast<uint32_t*>(&h1));
    }
}

// ---------------- one GEMM layer: K = NK16*16, A cols start at kbase ----------------
// 8 warps as 2row x 4col grid: warp tile = 32 rows x 32 cols. d[32] accumulators.
// W fragments LDG'd directly from gmem (fragment-ordered), depth-2 rotating prefetch.
// NO syncs inside.
template <int NK16>
__device__ __forceinline__ void run_layer(uint32_t smb,
                                          const unsigned char* __restrict__ w,
                                          int kbase, float* d, int lane, int warp) {
#pragma unroll
    for (int i = 0; i < 32; i++) d[i] = 0.f;

    int wrow = (warp & 1) * 32, cg = warp >> 1;
    const uint32_t aconst = smb + A_H +
        (uint32_t)((wrow + (lane & 7) + ((lane >> 3) & 1) * 8) * AS + (lane >> 4) * 8) * 2u;
    const unsigned char* wbase = w + (uint32_t)cg * 1024u + (uint32_t)lane * 32u;

    // depth-2 prefetch: v0 = step ks, v1 = step ks+1
    int4 v0a = __ldg((const int4*)(wbase));
    int4 v0b = __ldg((const int4*)(wbase + 16u));
    int4 v1a = __ldg((const int4*)(wbase + 4096u));
    int4 v1b = __ldg((const int4*)(wbase + 4096u + 16u));

#pragma unroll
    for (int ks = 0; ks < NK16; ks++) {
        int4 ca = v0a, cb = v0b;
        v0a = v1a; v0b = v1b;
        if (ks + 2 < NK16) {
            v1a = __ldg((const int4*)(wbase + (uint32_t)(ks + 2) * 4096u));
            v1b = __ldg((const int4*)(wbase + (uint32_t)(ks + 2) * 4096u + 16u));
        }
        uint32_t ah[2][4];
        uint32_t aaddr = aconst + (uint32_t)(kbase + ks * 16) * 2u;
        LDSM4(ah[0], aaddr);
        LDSM4(ah[1], aaddr + 16u * AS * 2u);
#pragma unroll
        for (int rt = 0; rt < 2; rt++) {
            MMA16816(d + rt * 16 + 0,  ah[rt], (uint32_t)ca.x, (uint32_t)ca.y);
            MMA16816(d + rt * 16 + 4,  ah[rt], (uint32_t)ca.z, (uint32_t)ca.w);
            MMA16816(d + rt * 16 + 8,  ah[rt], (uint32_t)cb.x, (uint32_t)cb.y);
            MMA16816(d + rt * 16 + 12, ah[rt], (uint32_t)cb.z, (uint32_t)cb.w);
        }
    }
}

// ---------------- LN stats core: bias + stats + cross-warp reduce (ONE sync) ----------------
__device__ __forceinline__ void ln_stats(unsigned char* sm, float* d, const float* bs,
                                         float* m, float* rv, int lane, int warp) {
    float2* part = (float2*)(sm + SM_PART);
    int wcol = (warp >> 1) * 32, cg = warp >> 1;
    int rbase = (warp & 1) * 32 + (lane >> 2);

    float s[4] = {0.f, 0.f, 0.f, 0.f}, q[4] = {0.f, 0.f, 0.f, 0.f};
#pragma unroll
    for (int rt = 0; rt < 2; rt++)
#pragma unroll
        for (int nt = 0; nt < 4; nt++) {
            int di = (rt * 4 + nt) * 4;
            int c0 = wcol + nt * 8 + (lane & 3) * 2;
            float x0 = d[di + 0] + bs[c0];
            float x1 = d[di + 1] + bs[c0 + 1];
            float x2 = d[di + 2] + bs[c0];
            float x3 = d[di + 3] + bs[c0 + 1];
            d[di + 0] = x0; d[di + 1] = x1; d[di + 2] = x2; d[di + 3] = x3;
            s[rt * 2]     += x0 + x1; q[rt * 2]     += x0 * x0 + x1 * x1;
            s[rt * 2 + 1] += x2 + x3; q[rt * 2 + 1] += x2 * x2 + x3 * x3;
        }
#pragma unroll
    for (int j = 0; j < 4; j++) {
        s[j] += __shfl_xor_sync(0xffffffffu, s[j], 1); s[j] += __shfl_xor_sync(0xffffffffu, s[j], 2);
        q[j] += __shfl_xor_sync(0xffffffffu, q[j], 1); q[j] += __shfl_xor_sync(0xffffffffu, q[j], 2);
    }
    if ((lane & 3) == 0) {
#pragma unroll
        for (int j = 0; j < 4; j++) {
            int row = rbase + (j & 1) * 8 + (j >> 1) * 16;
            part[row * 4 + cg] = make_float2(s[j], q[j]);
        }
    }
    __syncthreads();   // partials visible AND all mainloop A-LDSM done

#pragma unroll
    for (int j = 0; j < 4; j++) {
        int row = rbase + (j & 1) * 8 + (j >> 1) * 16;
        float2 p0 = part[row * 4 + 0], p1 = part[row * 4 + 1];
        float2 p2 = part[row * 4 + 2], p3 = part[row * 4 + 3];
        float sum = p0.x + p1.x + p2.x + p3.x;
        float qq  = p0.y + p1.y + p2.y + p3.y;
        m[j]  = sum * (1.f / 128.f);
        rv[j] = rsqrtf(qq * (1.f / 128.f) - m[j] * m[j] + EPSV);
    }
}

// ---------------- epilogue A: LN+ReLU -> fp16 back into A tile at dstcol (ends with sync) ----------------
__device__ __forceinline__ void epilogue_smem(unsigned char* sm, float* d, int L,
                                              int dstcol, int lane, int warp) {
    const float* bs  = (const float*)(sm + SM_BIAS) + L * 384;
    const float* gs  = bs + 128;
    const float* bes = bs + 256;
    float m[4], rv[4];
    ln_stats(sm, d, bs, m, rv, lane, warp);

    int wcol = (warp >> 1) * 32;
    int rbase = (warp & 1) * 32 + (lane >> 2);
#pragma unroll
    for (int rt = 0; rt < 2; rt++)
#pragma unroll
        for (int nt = 0; nt < 4; nt++) {
            int di = (rt * 4 + nt) * 4;
            int c0 = wcol + nt * 8 + (lane & 3) * 2;
            int j0 = rt * 2, j1 = rt * 2 + 1;
            float y0 = fmaxf(fmaf((d[di + 0] - m[j0]) * rv[j0], gs[c0],     bes[c0]),     0.f);
            float y1 = fmaxf(fmaf((d[di + 1] - m[j0]) * rv[j0], gs[c0 + 1], bes[c0 + 1]), 0.f);
            float y2 = fmaxf(fmaf((d[di + 2] - m[j1]) * rv[j1], gs[c0],     bes[c0]),     0.f);
            float y3 = fmaxf(fmaf((d[di + 3] - m[j1]) * rv[j1], gs[c0 + 1], bes[c0 + 1]), 0.f);
            int r0 = rbase + rt * 16, r1 = r0 + 8;
            __half2 h0 = __floats2half2_rn(y0, y1);
            __half2 h1 = __floats2half2_rn(y2, y3);
            *(uint32_t*)(sm + A_H + (uint32_t)(r0 * AS + dstcol + c0) * 2u) =
                *reinterpret_cast<uint32_t*>(&h0);
            *(uint32_t*)(sm + A_H + (uint32_t)(r1 * AS + dstcol + c0) * 2u) =
                *reinterpret_cast<uint32_t*>(&h1);
        }
    __syncthreads();   // A-tile writes visible to next layer
}

// ---------------- epilogue B: LN+ReLU -> direct emit (atomics to agg, or STG to out) ----------------
__device__ __forceinline__ void epilogue_emit(unsigned char* sm, float* d, int L,
                                              float* __restrict__ agg, const int* dsm,
                                              float* __restrict__ outp, long long row0,
                                              int nvalid, int lane, int warp) {
    const float* bs  = (const float*)(sm + SM_BIAS) + L * 384;
    const float* gs  = bs + 128;
    const float* bes = bs + 256;
    float m[4], rv[4];
    ln_stats(sm, d, bs, m, rv, lane, warp);

    int wcol = (warp >> 1) * 32;
    int rbase = (warp & 1) * 32 + (lane >> 2);
#pragma unroll
    for (int rt = 0; rt < 2; rt++) {
        int r0 = rbase + rt * 16, r1 = r0 + 8;
        bool ok0 = r0 < nvalid, ok1 = r1 < nvalid;
        size_t base0 = 0, base1 = 0;
        if (agg) {
            if (ok0) base0 = (size_t)dsm[r0] * 128;
            if (ok1) base1 = (size_t)dsm[r1] * 128;
        } else {
            base0 = (size_t)(row0 + r0) * 128;
            base1 = (size_t)(row0 + r1) * 128;
        }
#pragma unroll
        for (int nt = 0; nt < 4; nt++) {
            int di = (rt * 4 + nt) * 4;
            int c0 = wcol + nt * 8 + (lane & 3) * 2;
            int j0 = rt * 2, j1 = rt * 2 + 1;
            float y0 = fmaxf(fmaf((d[di + 0] - m[j0]) * rv[j0], gs[c0],     bes[c0]),     0.f);
            float y1 = fmaxf(fmaf((d[di + 1] - m[j0]) * rv[j0], gs[c0 + 1], bes[c0 + 1]), 0.f);
            float y2 = fmaxf(fmaf((d[di + 2] - m[j1]) * rv[j1], gs[c0],     bes[c0]),     0.f);
            float y3 = fmaxf(fmaf((d[di + 3] - m[j1]) * rv[j1], gs[c0 + 1], bes[c0 + 1]), 0.f);
            if (agg) {
                if (ok0) atomicAdd((float2*)(agg + base0 + c0), make_float2(y0, y1));
                if (ok1) atomicAdd((float2*)(agg + base1 + c0), make_float2(y2, y3));
            } else {
                if (ok0) *(float2*)(outp + base0 + c0) = make_float2(y0, y1);
                if (ok1) *(float2*)(outp + base1 + c0) = make_float2(y2, y3);
            }
        }
    }
}

// ---------------- edge kernel ----------------
__global__ __launch_bounds__(256, 3)
void edge_kernel(const float* __restrict__ h, const float* __restrict__ bond,
                 const int* __restrict__ src, const int* __restrict__ dst,
                 const unsigned char* __restrict__ wlev,
                 const float* __restrict__ b1, const float* __restrict__ g1, const float* __restrict__ be1,
                 const float* __restrict__ b2, const float* __restrict__ g2, const float* __restrict__ be2,
                 float* __restrict__ agg, int E) {
    extern __shared__ __align__(16) unsigned char sm[];
    uint32_t smb = smem_u32(sm);
    int t = threadIdx.x, lane = t & 31, warp = t >> 5;
    long long e0 = (long long)blockIdx.x * ROWS;
    int nvalid = (int)min((long long)ROWS, (long long)E - e0);

    int* ssm = (int*)(sm + SM_SRC);
    int* dsm = (int*)(sm + SM_DST);
    if (t < ROWS) {
        ssm[t] = (t < nvalid) ? src[e0 + t] : 0;
        dsm[t] = (t < nvalid) ? dst[e0 + t] : 0;
    }
    if (t < 128) {
        float* pb = (float*)(sm + SM_BIAS);
        pb[0 * 128 + t] = __ldg(b1 + t);  pb[1 * 128 + t] = __ldg(g1 + t);  pb[2 * 128 + t] = __ldg(be1 + t);
        pb[3 * 128 + t] = __ldg(b2 + t);  pb[4 * 128 + t] = __ldg(g2 + t);  pb[5 * 128 + t] = __ldg(be2 + t);
    }
    __syncthreads();

    gather64(sm, (const float4*)h, ssm, 0, 0, nvalid, t);
    gather64(sm, (const float4*)bond, nullptr, e0, 128, nvalid, t);
    __syncthreads();

    float d[32];
    run_layer<16>(smb, wlev + OFF_BW1, 0, d, lane, warp);
    epilogue_smem(sm, d, 0, 0, lane, warp);
    run_layer<8>(smb, wlev + OFF_BW2, 0, d, lane, warp);
    epilogue_emit(sm, d, 1, agg, dsm, nullptr, 0, nvalid, lane, warp);
}

// ---------------- node kernel ----------------
__global__ __launch_bounds__(256, 3)
void node_kernel(const float* __restrict__ ax, const float* __restrict__ aggin,
                 const unsigned char* __restrict__ wlev,
                 const float* __restrict__ sb1, const float* __restrict__ sg1, const float* __restrict__ sbe1,
                 const float* __restrict__ sb2, const float* __restrict__ sg2, const float* __restrict__ sbe2,
                 const float* __restrict__ hb, const float* __restrict__ hg, const float* __restrict__ hbe,
                 float* __restrict__ out, int N) {
    extern __shared__ __align__(16) unsigned char sm[];
    uint32_t smb = smem_u32(sm);
    int t = threadIdx.x, lane = t & 31, warp = t >> 5;
    long long n0 = (long long)blockIdx.x * ROWS;
    int nvalid = (int)min((long long)ROWS, (long long)N - n0);

    if (t < 128) {
        float* pb = (float*)(sm + SM_BIAS);
        pb[0 * 128 + t] = __ldg(sb1 + t); pb[1 * 128 + t] = __ldg(sg1 + t); pb[2 * 128 + t] = __ldg(sbe1 + t);
        pb[3 * 128 + t] = __ldg(sb2 + t); pb[4 * 128 + t] = __ldg(sg2 + t); pb[5 * 128 + t] = __ldg(sbe2 + t);
        pb[6 * 128 + t] = __ldg(hb + t);  pb[7 * 128 + t] = __ldg(hg + t);  pb[8 * 128 + t] = __ldg(hbe + t);
    }

    gather64(sm, (const float4*)ax, nullptr, n0, 0, nvalid, t);
    gather64(sm, (const float4*)aggin, nullptr, n0, 128, nvalid, t);
    __syncthreads();

    float d[32];
    run_layer<16>(smb, wlev + OFF_SW1, 0, d, lane, warp);
    epilogue_smem(sm, d, 0, 128, lane, warp);   // f1 -> cols 128..255 (keep ax)
    run_layer<8>(smb, wlev + OFF_SW2, 128, d, lane, warp);
    epilogue_smem(sm, d, 1, 128, lane, warp);   // f2 -> cols 128..255
    run_layer<16>(smb, wlev + OFF_HW, 0, d, lane, warp);
    epilogue_emit(sm, d, 2, nullptr, nullptr, out, n0, nvalid, lane, warp);
}

// ---------------- weight prep: fp32 W[K][128] -> mma B-fragment-ordered fp16 ----------------
__global__ void prep_kernel(const float* __restrict__ bW1, const float* __restrict__ bW2,
                            const float* __restrict__ sW1, const float* __restrict__ sW2,
                            const float* __restrict__ hW) {
    int level = blockIdx.y, bx = blockIdx.x, t = threadIdx.x;
    const float* W; int ks; uint32_t off; int K;
    if (bx < 16)      { W = bW1; ks = bx;      off = OFF_BW1; K = 256; }
    else if (bx < 24) { W = bW2; ks = bx - 16; off = OFF_BW2; K = 128; }
    else if (bx < 40) { W = sW1; ks = bx - 24; off = OFF_SW1; K = 256; }
    else if (bx < 48) { W = sW2; ks = bx - 40; off = OFF_SW2; K = 128; }
    else              { W = hW;  ks = bx - 48; off = OFF_HW;  K = 256; }

    const float* wsrc = W + (size_t)level * K * 128;
    int cg = t >> 5, lane = t & 31;
    unsigned char* dl = g_Wprep + (size_t)level * WLEVEL + off
                      + (size_t)ks * 4096u + (uint32_t)cg * 1024u + (uint32_t)lane * 32u;
    int kb = ks * 16 + (lane & 3) * 2;
#pragma unroll
    for (int nt = 0; nt < 4; nt++) {
        int n = cg * 32 + nt * 8 + (lane >> 2);
        __half2 b0 = __halves2half2(__float2half_rn(wsrc[kb * 128 + n]),
                                    __float2half_rn(wsrc[(kb + 1) * 128 + n]));
        __half2 b1 = __halves2half2(__float2half_rn(wsrc[(kb + 8) * 128 + n]),
                                    __float2half_rn(wsrc[(kb + 9) * 128 + n]));
        *(uint32_t*)(dl + nt * 8)     = *reinterpret_cast<uint32_t*>(&b0);
        *(uint32_t*)(dl + nt * 8 + 4) = *reinterpret_cast<uint32_t*>(&b1);
    }
}

// ---------------- kernel_launch ----------------
extern "C" void kernel_launch(void* const* d_in, const int* in_sizes, int n_in,
                              void* d_out, int out_size) {
    const float* subtree_h_top = (const float*)d_in[0];
    const float* atom_x_1      = (const float*)d_in[1];
    const float* atom_x_0      = (const float*)d_in[2];
    const float* bond_x_2      = (const float*)d_in[3];
    const float* bond_x_1      = (const float*)d_in[4];
    const float* branch_W1     = (const float*)d_in[5];
    const float* branch_b1     = (const float*)d_in[6];
    const float* branch_g1     = (const float*)d_in[7];
    const float* branch_beta1  = (const float*)d_in[8];
    const float* branch_W2     = (const float*)d_in[9];
    const float* branch_b2     = (const float*)d_in[10];
    const float* branch_g2     = (const float*)d_in[11];
    const float* branch_beta2  = (const float*)d_in[12];
    const float* sub_W1        = (const float*)d_in[13];
    const float* sub_b1        = (const float*)d_in[14];
    const float* sub_g1        = (const float*)d_in[15];
    const float* sub_beta1     = (const float*)d_in[16];
    const float* sub_W2        = (const float*)d_in[17];
    const float* sub_b2        = (const float*)d_in[18];
    const float* sub_g2        = (const float*)d_in[19];
    const float* sub_beta2     = (const float*)d_in[20];
    const float* head_W        = (const float*)d_in[21];
    const float* head_b        = (const float*)d_in[22];
    const float* head_g        = (const float*)d_in[23];
    const float* head_beta     = (const float*)d_in[24];
    const int*   src_2         = (const int*)d_in[25];
    const int*   dst_2         = (const int*)d_in[26];
    const int*   src_1         = (const int*)d_in[27];
    const int*   dst_1         = (const int*)d_in[28];

    const int n2 = in_sizes[0] / D;
    const int n1 = in_sizes[1] / D;
    const int n0 = in_sizes[2] / D;

    float* agg; cudaGetSymbolAddress((void**)&agg, g_agg);
    float* h1;  cudaGetSymbolAddress((void**)&h1,  g_h1);
    unsigned char* wprep; cudaGetSymbolAddress((void**)&wprep, g_Wprep);
    float* out = (float*)d_out;

    static bool attr_done = false;
    if (!attr_done) {
        cudaFuncSetAttribute(edge_kernel, cudaFuncAttributeMaxDynamicSharedMemorySize, SMEM_DYN);
        cudaFuncSetAttribute(node_kernel, cudaFuncAttributeMaxDynamicSharedMemorySize, SMEM_DYN);
        attr_done = true;
    }

    const int V = D;

    prep_kernel<<<dim3(64, 2), 128>>>(branch_W1, branch_W2, sub_W1, sub_W2, head_W);

    // level 0: n2 edges -> n1 nodes
    cudaMemsetAsync(agg, 0, (size_t)n1 * D * sizeof(float));
    edge_kernel<<<(n2 + ROWS - 1) / ROWS, 256, SMEM_DYN>>>(
        subtree_h_top, bond_x_2, src_2, dst_2, wprep,
        branch_b1, branch_g1, branch_beta1,
        branch_b2, branch_g2, branch_beta2, agg, n2);
    node_kernel<<<(n1 + ROWS - 1) / ROWS, 256, SMEM_DYN>>>(
        atom_x_1, agg, wprep,
        sub_b1, sub_g1, sub_beta1,
        sub_b2, sub_g2, sub_beta2,
        head_b, head_g, head_beta, h1, n1);

    // level 1: n1 edges -> n0 nodes
    cudaMemsetAsync(agg, 0, (size_t)n0 * D * sizeof(float));
    edge_kernel<<<(n1 + ROWS - 1) / ROWS, 256, SMEM_DYN>>>(
        h1, bond_x_1, src_1, dst_1, wprep + WLEVEL,
        branch_b1 + V, branch_g1 + V, branch_beta1 + V,
        branch_b2 + V, branch_g2 + V, branch_beta2 + V, agg, n1);
    node_kernel<<<(n0 + ROWS - 1) / ROWS, 256, SMEM_DYN>>>(
        atom_x_0, agg, wprep + WLEVEL,
        sub_b1 + V, sub_g1 + V, sub_beta1 + V,
        sub_b2 + V, sub_g2 + V, sub_beta2 + V,
        head_b + V, head_g + V, head_beta + V, out, n0);
}